// round 11
// baseline (speedup 1.0000x reference)
#include <cuda_runtime.h>
#include <cuda_fp16.h>
#include <cstdint>

// Spatial RNN, 4 dirs, R=8 steps, C=64. f16 mma.sync, register-resident state.
// x:(8,192,192,64) fp32; W_*:(64,64); out:(8,192,192,256)
//
// One CTA per scan line (3072 CTAs x 384 thr, 12 warps). Warp = m16 x n64.
// The C-fragment channel packing equals the A-fragment packing, so the
// relu->shift->next-step conversion is pure row movement: lane +-4 shuffles,
// with the single row crossing each warp boundary exchanged via a 128B smem
// edge buffer (double-buffered, one barrier/step). No STSM/LDSM in the loop.

#define STRB 144                   // Xb row stride (bytes)
#define BROWS 194
#define BUFB (BROWS * STRB)        // 27936
#define EPAR 1664                  // 13 edge rows * 128B
#define SMEM_DYN (BUFB + 4 * EPAR + 64)

static __device__ __forceinline__ uint32_t smem_u32(const void* p) {
    uint32_t a;
    asm("{ .reg .u64 t; cvta.to.shared.u64 t, %1; cvt.u32.u64 %0, t; }" : "=r"(a) : "l"(p));
    return a;
}
static __device__ __forceinline__ uint32_t pkh2(float lo, float hi) {
    uint32_t r;
    asm("cvt.rn.f16x2.f32 %0, %1, %2;" : "=r"(r) : "f"(hi), "f"(lo));
    return r;
}
static __device__ __forceinline__ uint32_t hmax2z(uint32_t v) {
    uint32_t r;
    asm("max.f16x2 %0, %1, %2;" : "=r"(r) : "r"(v), "r"(0u));
    return r;
}
static __device__ __forceinline__ uint32_t hadd2(uint32_t a, uint32_t b) {
    uint32_t r;
    asm("add.f16x2 %0, %1, %2;" : "=r"(r) : "r"(a), "r"(b));
    return r;
}
static __device__ __forceinline__ void unpkh2(uint32_t v, float& lo, float& hi) {
    asm("{ .reg .f16 l, h; mov.b32 {l, h}, %2; cvt.f32.f16 %0, l; cvt.f32.f16 %1, h; }"
        : "=f"(lo), "=f"(hi) : "r"(v));
}
static __device__ __forceinline__ void ldsm4(uint32_t a[4], uint32_t addr) {
    asm volatile("ldmatrix.sync.aligned.m8n8.x4.shared.b16 {%0,%1,%2,%3}, [%4];"
                 : "=r"(a[0]), "=r"(a[1]), "=r"(a[2]), "=r"(a[3]) : "r"(addr));
}
static __device__ __forceinline__ void mma16816h(uint32_t c[2], const uint32_t a[4],
                                                 const uint32_t b[2]) {
    asm volatile(
        "mma.sync.aligned.m16n8k16.row.col.f16.f16.f16.f16 "
        "{%0,%1}, {%2,%3,%4,%5}, {%6,%7}, {%0,%1};"
        : "+r"(c[0]), "+r"(c[1])
        : "r"(a[0]), "r"(a[1]), "r"(a[2]), "r"(a[3]), "r"(b[0]), "r"(b[1]));
}
static __device__ __forceinline__ void sts128(uint32_t addr, uint32_t a, uint32_t b,
                                              uint32_t c, uint32_t d) {
    asm volatile("st.shared.v4.b32 [%0], {%1,%2,%3,%4};"
                 :: "r"(addr), "r"(a), "r"(b), "r"(c), "r"(d) : "memory");
}
static __device__ __forceinline__ uint32_t lds32(uint32_t addr) {
    uint32_t v;
    asm volatile("ld.shared.b32 %0, [%1];" : "=r"(v) : "r"(addr));
    return v;
}
static __device__ __forceinline__ void sts32(uint32_t addr, uint32_t v) {
    asm volatile("st.shared.b32 [%0], %1;" :: "r"(addr), "r"(v) : "memory");
}

extern "C" __global__ void __launch_bounds__(384, 1)
rnn_kernel(const float* __restrict__ x,
           const float* __restrict__ W_left, const float* __restrict__ W_right,
           const float* __restrict__ W_up,   const float* __restrict__ W_down,
           float* __restrict__ out)
{
    extern __shared__ char dsm[];
    const uint32_t base  = (smem_u32(dsm) + 15u) & ~15u;
    const uint32_t Xb    = base;               // f16 x, rows 0..193 (guards 0,193)
    const uint32_t EDGE0 = base + BUFB;        // dir0 edges [2 par][13 rows][128B]
    const uint32_t EDGE1 = EDGE0 + 2 * EPAR;   // dir1 edges

    const int tid  = threadIdx.x;
    const int lane = tid & 31;
    const int warp = tid >> 5;                 // 0..11, m0 = 16*warp
    const int gID  = lane >> 2;
    const int tg   = lane & 3;
    const int m0   = warp * 16;

    // --- geometry ---
    long inBase, outBase;
    int pixIn, pixOut, chBase;
    const float *Wfp, *Wbp;
    {
        int l = blockIdx.x;
        if (l < 1536) {                            // horizontal row
            inBase  = (long)l * (192 * 64);
            outBase = (long)l * (192 * 256);
            pixIn = 64;  pixOut = 256;  chBase = 0;
            Wfp = W_left;  Wbp = W_right;
        } else {                                    // vertical column
            int l2 = l - 1536;
            int b = l2 / 192, w = l2 % 192;
            inBase  = (long)b * (192 * 192 * 64)  + (long)w * 64;
            outBase = (long)b * (192 * 192 * 256) + (long)w * 256;
            pixIn = 192 * 64;  pixOut = 192 * 256;  chBase = 128;
            Wfp = W_up;  Wbp = W_down;
        }
    }
    const float* xl = x + inBase;
    float* ol = out + outBase;

    // --- zero Xb guard rows + edge guard rows ---
    if (tid < 36) {
        sts32(Xb + tid * 4, 0);
        sts32(Xb + 193 * STRB + tid * 4, 0);
    }
    if (tid < 32) {
        sts32(EDGE0 + 0 * EPAR + tid * 4, 0);            // dir0 guard: row 0
        sts32(EDGE0 + 1 * EPAR + tid * 4, 0);
        sts32(EDGE1 + 0 * EPAR + 12 * 128 + tid * 4, 0); // dir1 guard: row 12
        sts32(EDGE1 + 1 * EPAR + 12 * 128 + tid * 4, 0);
    }

    // --- load x (f16) into Xb rows 1..192 ---
    #pragma unroll
    for (int p = 0; p < 2; p++) {
        int i = tid + p * 384;                  // 0..767
        int r = i >> 2;
        int c0 = (i & 3) * 16;
        const float* xp = xl + (long)r * pixIn + c0;
        uint32_t h[8];
        #pragma unroll
        for (int j = 0; j < 4; j++) {
            float4 v = *reinterpret_cast<const float4*>(xp + j * 4);
            h[2 * j]     = pkh2(v.x, v.y);
            h[2 * j + 1] = pkh2(v.z, v.w);
        }
        uint32_t a0 = Xb + (r + 1) * STRB + c0 * 2;
        sts128(a0,      h[0], h[1], h[2], h[3]);
        sts128(a0 + 16, h[4], h[5], h[6], h[7]);
    }

    const int lrow = (lane & 7) + ((lane >> 3) & 1) * 8;
    const int lcol = (lane >> 4) * 16;
    __syncthreads();

    #pragma unroll 1
    for (int dir = 0; dir < 2; dir++) {
        const float* Wg = dir ? Wbp : Wfp;
        const int shift = dir ? 1 : -1;            // fwd reads r-1, bwd reads r+1

        // --- B fragments in registers (f16x2), from gmem (L2-hot) ---
        uint32_t b[4][8][2];
        #pragma unroll
        for (int kc = 0; kc < 4; kc++)
            #pragma unroll
            for (int nt = 0; nt < 8; nt++) {
                int k0 = kc * 16 + 2 * tg;
                int n  = nt * 8 + gID;
                b[kc][nt][0] = pkh2(__ldg(&Wg[(k0)     * 64 + n]), __ldg(&Wg[(k0 + 1) * 64 + n]));
                b[kc][nt][1] = pkh2(__ldg(&Wg[(k0 + 8) * 64 + n]), __ldg(&Wg[(k0 + 9) * 64 + n]));
            }

        uint32_t acc[8][2];
        #pragma unroll
        for (int nt = 0; nt < 8; nt++) { acc[nt][0] = 0u; acc[nt][1] = 0u; }

        // --- initial A fragments: shifted x from Xb ---
        uint32_t a[4][4];
        {
            const uint32_t ldOff = (uint32_t)((m0 + lrow + shift + 1) * STRB + lcol);
            #pragma unroll
            for (int kc = 0; kc < 4; kc++)
                ldsm4(a[kc], Xb + ldOff + kc * 32);
        }

        #pragma unroll 1
        for (int s = 0; s < 8; s++) {
            uint32_t Cf[8][2];
            #pragma unroll
            for (int nt = 0; nt < 8; nt++) { Cf[nt][0] = 0u; Cf[nt][1] = 0u; }

            #pragma unroll
            for (int kc = 0; kc < 4; kc++)
                #pragma unroll
                for (int nt = 0; nt < 8; nt++)
                    mma16816h(Cf[nt], a[kc], b[kc][nt]);

            // relu (h overwrites Cf) + accumulate
            uint32_t (&h)[8][2] = Cf;
            #pragma unroll
            for (int nt = 0; nt < 8; nt++) {
                h[nt][0] = hmax2z(Cf[nt][0]);
                h[nt][1] = hmax2z(Cf[nt][1]);
                acc[nt][0] = hadd2(acc[nt][0], h[nt][0]);
                acc[nt][1] = hadd2(acc[nt][1], h[nt][1]);
            }

            if (s == 7) break;
            const uint32_t par = (uint32_t)(s & 1) * EPAR;

            if (dir == 0) {
                // warp w's last row (m0+15) feeds warp w+1 -> edge slot w+1
                if (gID == 7) {
                    uint32_t ea = EDGE0 + par + (warp + 1) * 128 + tg * 4;
                    #pragma unroll
                    for (int nt = 0; nt < 8; nt++)
                        sts32(ea + nt * 16, h[nt][1]);
                }
                __syncthreads();
                uint32_t eb = EDGE0 + par + warp * 128 + tg * 4;
                #pragma unroll
                for (int kc = 0; kc < 4; kc++) {
                    uint32_t u0 = __shfl_up_sync(0xffffffffu, h[2 * kc][0], 4);
                    uint32_t u1 = __shfl_up_sync(0xffffffffu, h[2 * kc][1], 4);
                    uint32_t f1 = __shfl_sync(0xffffffffu, h[2 * kc][0], 28 + tg);
                    uint32_t v0 = __shfl_up_sync(0xffffffffu, h[2 * kc + 1][0], 4);
                    uint32_t v1 = __shfl_up_sync(0xffffffffu, h[2 * kc + 1][1], 4);
                    uint32_t g1 = __shfl_sync(0xffffffffu, h[2 * kc + 1][0], 28 + tg);
                    uint32_t e0 = lds32(eb + (2 * kc) * 16);
                    uint32_t e2 = lds32(eb + (2 * kc + 1) * 16);
                    a[kc][0] = (gID == 0) ? e0 : u0;
                    a[kc][1] = (gID == 0) ? f1 : u1;
                    a[kc][2] = (gID == 0) ? e2 : v0;
                    a[kc][3] = (gID == 0) ? g1 : v1;
                }
            } else {
                // warp w's first row (m0) feeds warp w-1 -> edge slot w
                if (gID == 0) {
                    uint32_t ea = EDGE1 + par + warp * 128 + tg * 4;
                    #pragma unroll
                    for (int nt = 0; nt < 8; nt++)
                        sts32(ea + nt * 16, h[nt][0]);
                }
                __syncthreads();
                uint32_t eb = EDGE1 + par + (warp + 1) * 128 + tg * 4;
                #pragma unroll
                for (int kc = 0; kc < 4; kc++) {
                    uint32_t u0 = __shfl_down_sync(0xffffffffu, h[2 * kc][0], 4);
                    uint32_t u1 = __shfl_down_sync(0xffffffffu, h[2 * kc][1], 4);
                    uint32_t f0 = __shfl_sync(0xffffffffu, h[2 * kc][1], tg);
                    uint32_t v0 = __shfl_down_sync(0xffffffffu, h[2 * kc + 1][0], 4);
                    uint32_t v1 = __shfl_down_sync(0xffffffffu, h[2 * kc + 1][1], 4);
                    uint32_t g0 = __shfl_sync(0xffffffffu, h[2 * kc + 1][1], tg);
                    uint32_t e1 = lds32(eb + (2 * kc) * 16);
                    uint32_t e3 = lds32(eb + (2 * kc + 1) * 16);
                    a[kc][0] = (gID == 7) ? f0 : u0;
                    a[kc][1] = (gID == 7) ? e1 : u1;
                    a[kc][2] = (gID == 7) ? g0 : v0;
                    a[kc][3] = (gID == 7) ? e3 : v1;
                }
            }
        }

        // --- epilogue: out = x + acc ---
        const int cb = chBase + dir * 64;
        #pragma unroll
        for (int hh = 0; hh < 2; hh++) {
            int gr = m0 + gID + hh * 8;
            const float* xp = xl + (long)gr * pixIn;
            float* op = ol + (long)gr * pixOut + cb;
            #pragma unroll
            for (int nt = 0; nt < 8; nt++) {
                int col = nt * 8 + 2 * tg;
                float a0, a1;
                unpkh2(acc[nt][hh], a0, a1);
                float2 xv = *reinterpret_cast<const float2*>(xp + col);
                float2 o = make_float2(xv.x + a0, xv.y + a1);
                *reinterpret_cast<float2*>(op + col) = o;
            }
        }
        // no cross-dir smem hazard: dirs use separate edge buffers, Xb read-only
    }
}

extern "C" void kernel_launch(void* const* d_in, const int* in_sizes, int n_in,
                              void* d_out, int out_size)
{
    const float* x  = (const float*)d_in[0];
    const float* wl = (const float*)d_in[1];
    const float* wr = (const float*)d_in[2];
    const float* wu = (const float*)d_in[3];
    const float* wd = (const float*)d_in[4];
    float* out = (float*)d_out;

    cudaFuncSetAttribute(rnn_kernel, cudaFuncAttributeMaxDynamicSharedMemorySize, SMEM_DYN);
    rnn_kernel<<<3072, 384, SMEM_DYN>>>(x, wl, wr, wu, wd, out);
}

// round 12
// speedup vs baseline: 1.4217x; 1.4217x over previous
#include <cuda_runtime.h>
#include <cuda_fp16.h>
#include <cstdint>

// Spatial RNN, 4 dirs, R=8 steps, C=64. f16 mma.sync (f16 accum) + LDSM/STSM.
// x:(8,192,192,64) fp32; W_*:(64,64); out:(8,192,192,256)
//
// One CTA per scan line (3072 CTAs x 256 thr, 8 warps, m48xn32 warp tiles).
// R12: BOTH directions advance in the same step loop (separate ping-pong
// buffers, B-regs and accumulators) -> two independent mma streams per warp
// between barriers, and half the barriers of R9. One CTA/SM (regs ~180),
// smem = Xb + P0/P1 (dir0) + Q0/Q1 (dir1) = 5 x 27936B.

#define STRB 144                 // bytes per buffer row (64 f16 + pad)
#define BROWS 194                // rows 0..193, guards at 0 and 193
#define BUFB (BROWS * STRB)      // 27936 bytes
#define SMEM_DYN (5 * BUFB + 64) // 139744

static __device__ __forceinline__ uint32_t smem_u32(const void* p) {
    uint32_t a;
    asm("{ .reg .u64 t; cvta.to.shared.u64 t, %1; cvt.u32.u64 %0, t; }" : "=r"(a) : "l"(p));
    return a;
}
static __device__ __forceinline__ uint32_t pkh2(float lo, float hi) {
    uint32_t r;
    asm("cvt.rn.f16x2.f32 %0, %1, %2;" : "=r"(r) : "f"(hi), "f"(lo));
    return r;
}
static __device__ __forceinline__ uint32_t hmax2z(uint32_t v) {
    uint32_t r;
    asm("max.f16x2 %0, %1, %2;" : "=r"(r) : "r"(v), "r"(0u));
    return r;
}
static __device__ __forceinline__ uint32_t hadd2(uint32_t a, uint32_t b) {
    uint32_t r;
    asm("add.f16x2 %0, %1, %2;" : "=r"(r) : "r"(a), "r"(b));
    return r;
}
static __device__ __forceinline__ void unpkh2(uint32_t v, float& lo, float& hi) {
    asm("{ .reg .f16 l, h; mov.b32 {l, h}, %2; cvt.f32.f16 %0, l; cvt.f32.f16 %1, h; }"
        : "=f"(lo), "=f"(hi) : "r"(v));
}
static __device__ __forceinline__ void ldsm4(uint32_t a[4], uint32_t addr) {
    asm volatile("ldmatrix.sync.aligned.m8n8.x4.shared.b16 {%0,%1,%2,%3}, [%4];"
                 : "=r"(a[0]), "=r"(a[1]), "=r"(a[2]), "=r"(a[3]) : "r"(addr));
}
static __device__ __forceinline__ void stsm4(uint32_t addr, uint32_t r0, uint32_t r1,
                                             uint32_t r2, uint32_t r3) {
    asm volatile("stmatrix.sync.aligned.m8n8.x4.shared.b16 [%0], {%1,%2,%3,%4};"
                 :: "r"(addr), "r"(r0), "r"(r1), "r"(r2), "r"(r3) : "memory");
}
static __device__ __forceinline__ void mma16816h(uint32_t c[2], const uint32_t a[4],
                                                 const uint32_t b[2]) {
    asm volatile(
        "mma.sync.aligned.m16n8k16.row.col.f16.f16.f16.f16 "
        "{%0,%1}, {%2,%3,%4,%5}, {%6,%7}, {%0,%1};"
        : "+r"(c[0]), "+r"(c[1])
        : "r"(a[0]), "r"(a[1]), "r"(a[2]), "r"(a[3]), "r"(b[0]), "r"(b[1]));
}
static __device__ __forceinline__ void sts128(uint32_t addr, uint32_t a, uint32_t b,
                                              uint32_t c, uint32_t d) {
    asm volatile("st.shared.v4.b32 [%0], {%1,%2,%3,%4};"
                 :: "r"(addr), "r"(a), "r"(b), "r"(c), "r"(d) : "memory");
}
static __device__ __forceinline__ void sts32(uint32_t addr, uint32_t v) {
    asm volatile("st.shared.b32 [%0], %1;" :: "r"(addr), "r"(v) : "memory");
}

extern "C" __global__ void __launch_bounds__(256, 1)
rnn_kernel(const float* __restrict__ x,
           const float* __restrict__ W_left, const float* __restrict__ W_right,
           const float* __restrict__ W_up,   const float* __restrict__ W_down,
           float* __restrict__ out)
{
    extern __shared__ char dsm[];
    const uint32_t base = (smem_u32(dsm) + 15u) & ~15u;
    const uint32_t Xb = base;              // persistent f16 x
    const uint32_t P0 = base + BUFB;       // dir0 ping-pong
    const uint32_t P1 = base + 2 * BUFB;
    const uint32_t Q0 = base + 3 * BUFB;   // dir1 ping-pong
    const uint32_t Q1 = base + 4 * BUFB;

    const int tid  = threadIdx.x;
    const int lane = tid & 31;
    const int warp = tid >> 5;
    const int mg   = warp & 3;        // 4 m-groups of 48 rows
    const int ng   = warp >> 2;       // 2 n-groups of 32 cols
    const int gID  = lane >> 2;
    const int tg   = lane & 3;
    const int m0   = mg * 48;
    const int n0   = ng * 32;

    // --- geometry ---
    long inBase, outBase;
    int pixIn, pixOut, chBase;
    const float *Wfp, *Wbp;
    {
        int l = blockIdx.x;
        if (l < 1536) {                            // horizontal row
            inBase  = (long)l * (192 * 64);
            outBase = (long)l * (192 * 256);
            pixIn = 64;  pixOut = 256;  chBase = 0;
            Wfp = W_left;  Wbp = W_right;
        } else {                                    // vertical column
            int l2 = l - 1536;
            int b = l2 / 192, w = l2 % 192;
            inBase  = (long)b * (192 * 192 * 64)  + (long)w * 64;
            outBase = (long)b * (192 * 192 * 256) + (long)w * 256;
            pixIn = 192 * 64;  pixOut = 192 * 256;  chBase = 128;
            Wfp = W_up;  Wbp = W_down;
        }
    }
    const float* xl = x + inBase;
    float* ol = out + outBase;

    // --- zero guard rows (rows 0 and 193 of all five buffers) ---
    if (tid < 36) {
        sts32(Xb + tid * 4, 0);  sts32(Xb + 193 * STRB + tid * 4, 0);
        sts32(P0 + tid * 4, 0);  sts32(P0 + 193 * STRB + tid * 4, 0);
        sts32(P1 + tid * 4, 0);  sts32(P1 + 193 * STRB + tid * 4, 0);
        sts32(Q0 + tid * 4, 0);  sts32(Q0 + 193 * STRB + tid * 4, 0);
        sts32(Q1 + tid * 4, 0);  sts32(Q1 + 193 * STRB + tid * 4, 0);
    }

    // --- load x (f16) into Xb rows 1..192 ---
    #pragma unroll
    for (int p = 0; p < 3; p++) {
        int i = tid + p * 256;                  // 0..767
        int r = i >> 2;
        int c0 = (i & 3) * 16;
        const float* xp = xl + (long)r * pixIn + c0;
        uint32_t h[8];
        #pragma unroll
        for (int j = 0; j < 4; j++) {
            float4 v = *reinterpret_cast<const float4*>(xp + j * 4);
            h[2 * j]     = pkh2(v.x, v.y);
            h[2 * j + 1] = pkh2(v.z, v.w);
        }
        uint32_t a0 = Xb + (r + 1) * STRB + c0 * 2;
        sts128(a0,      h[0], h[1], h[2], h[3]);
        sts128(a0 + 16, h[4], h[5], h[6], h[7]);
    }

    // LDSM/STSM per-thread row/col decomposition
    const int lrow = (lane & 7) + ((lane >> 3) & 1) * 8;
    const int lcol = (lane >> 4) * 16;
    const uint32_t stOff = (uint32_t)((m0 + lrow + 1) * STRB + lcol) + (uint32_t)(n0 * 2);
    // dir0 reads r-1 -> buffer row (m0+lrow); dir1 reads r+1 -> (m0+lrow+2)
    const uint32_t ldOff0 = (uint32_t)((m0 + lrow)     * STRB + lcol);
    const uint32_t ldOff1 = (uint32_t)((m0 + lrow + 2) * STRB + lcol);

    // --- B fragments for BOTH dirs in registers (f16x2) ---
    uint32_t b0[4][4][2], b1[4][4][2];
    #pragma unroll
    for (int kc = 0; kc < 4; kc++)
        #pragma unroll
        for (int nt = 0; nt < 4; nt++) {
            int k0 = kc * 16 + 2 * tg;
            int n  = n0 + nt * 8 + gID;
            b0[kc][nt][0] = pkh2(__ldg(&Wfp[(k0)     * 64 + n]), __ldg(&Wfp[(k0 + 1) * 64 + n]));
            b0[kc][nt][1] = pkh2(__ldg(&Wfp[(k0 + 8) * 64 + n]), __ldg(&Wfp[(k0 + 9) * 64 + n]));
            b1[kc][nt][0] = pkh2(__ldg(&Wbp[(k0)     * 64 + n]), __ldg(&Wbp[(k0 + 1) * 64 + n]));
            b1[kc][nt][1] = pkh2(__ldg(&Wbp[(k0 + 8) * 64 + n]), __ldg(&Wbp[(k0 + 9) * 64 + n]));
        }

    uint32_t acc0[3][4][2], acc1[3][4][2];
    #pragma unroll
    for (int mt = 0; mt < 3; mt++)
        #pragma unroll
        for (int nt = 0; nt < 4; nt++) {
            acc0[mt][nt][0] = 0u;  acc0[mt][nt][1] = 0u;
            acc1[mt][nt][0] = 0u;  acc1[mt][nt][1] = 0u;
        }

    __syncthreads();

    uint32_t src0 = Xb, dst0 = P0;
    uint32_t src1 = Xb, dst1 = Q0;

    #pragma unroll 1
    for (int s = 0; s < 8; s++) {
        const bool last = (s == 7);

        #pragma unroll
        for (int mt = 0; mt < 3; mt++) {
            // ---- dir0 (m-tile mt) ----
            {
                uint32_t a[4][4];
                #pragma unroll
                for (int kc = 0; kc < 4; kc++)
                    ldsm4(a[kc], src0 + ldOff0 + mt * (16 * STRB) + kc * 32);
                uint32_t Cf[4][2];
                #pragma unroll
                for (int nt = 0; nt < 4; nt++) { Cf[nt][0] = 0u; Cf[nt][1] = 0u; }
                #pragma unroll
                for (int kc = 0; kc < 4; kc++)
                    #pragma unroll
                    for (int nt = 0; nt < 4; nt++)
                        mma16816h(Cf[nt], a[kc], b0[kc][nt]);
                uint32_t h[4][2];
                #pragma unroll
                for (int nt = 0; nt < 4; nt++) {
                    h[nt][0] = hmax2z(Cf[nt][0]);
                    h[nt][1] = hmax2z(Cf[nt][1]);
                    acc0[mt][nt][0] = hadd2(acc0[mt][nt][0], h[nt][0]);
                    acc0[mt][nt][1] = hadd2(acc0[mt][nt][1], h[nt][1]);
                }
                if (!last) {
                    uint32_t sa = dst0 + stOff + mt * (16 * STRB);
                    stsm4(sa,      h[0][0], h[0][1], h[1][0], h[1][1]);
                    stsm4(sa + 32, h[2][0], h[2][1], h[3][0], h[3][1]);
                }
            }
            // ---- dir1 (m-tile mt) ----
            {
                uint32_t a[4][4];
                #pragma unroll
                for (int kc = 0; kc < 4; kc++)
                    ldsm4(a[kc], src1 + ldOff1 + mt * (16 * STRB) + kc * 32);
                uint32_t Cf[4][2];
                #pragma unroll
                for (int nt = 0; nt < 4; nt++) { Cf[nt][0] = 0u; Cf[nt][1] = 0u; }
                #pragma unroll
                for (int kc = 0; kc < 4; kc++)
                    #pragma unroll
                    for (int nt = 0; nt < 4; nt++)
                        mma16816h(Cf[nt], a[kc], b1[kc][nt]);
                uint32_t h[4][2];
                #pragma unroll
                for (int nt = 0; nt < 4; nt++) {
                    h[nt][0] = hmax2z(Cf[nt][0]);
                    h[nt][1] = hmax2z(Cf[nt][1]);
                    acc1[mt][nt][0] = hadd2(acc1[mt][nt][0], h[nt][0]);
                    acc1[mt][nt][1] = hadd2(acc1[mt][nt][1], h[nt][1]);
                }
                if (!last) {
                    uint32_t sa = dst1 + stOff + mt * (16 * STRB);
                    stsm4(sa,      h[0][0], h[0][1], h[1][0], h[1][1]);
                    stsm4(sa + 32, h[2][0], h[2][1], h[3][0], h[3][1]);
                }
            }
        }

        if (!last) __syncthreads();
        src0 = dst0;  dst0 = (dst0 == P0) ? P1 : P0;
        src1 = dst1;  dst1 = (dst1 == Q0) ? Q1 : Q0;
    }

    // --- epilogue: out = x + acc, both dirs ---
    #pragma unroll
    for (int mt = 0; mt < 3; mt++) {
        #pragma unroll
        for (int hh = 0; hh < 2; hh++) {
            int gr = m0 + mt * 16 + gID + hh * 8;
            const float* xp = xl + (long)gr * pixIn;
            float* op0 = ol + (long)gr * pixOut + chBase;
            #pragma unroll
            for (int nt = 0; nt < 4; nt++) {
                int col = n0 + nt * 8 + 2 * tg;
                float2 xv = *reinterpret_cast<const float2*>(xp + col);
                float a0, a1;
                unpkh2(acc0[mt][nt][hh], a0, a1);
                *reinterpret_cast<float2*>(op0 + col) =
                    make_float2(xv.x + a0, xv.y + a1);
                unpkh2(acc1[mt][nt][hh], a0, a1);
                *reinterpret_cast<float2*>(op0 + 64 + col) =
                    make_float2(xv.x + a0, xv.y + a1);
            }
        }
    }
}

extern "C" void kernel_launch(void* const* d_in, const int* in_sizes, int n_in,
                              void* d_out, int out_size)
{
    const float* x  = (const float*)d_in[0];
    const float* wl = (const float*)d_in[1];
    const float* wr = (const float*)d_in[2];
    const float* wu = (const float*)d_in[3];
    const float* wd = (const float*)d_in[4];
    float* out = (float*)d_out;

    cudaFuncSetAttribute(rnn_kernel, cudaFuncAttributeMaxDynamicSharedMemorySize, SMEM_DYN);
    rnn_kernel<<<3072, 256, SMEM_DYN>>>(x, wl, wr, wu, wd, out);
}

// round 13
// speedup vs baseline: 1.6569x; 1.1654x over previous
#include <cuda_runtime.h>
#include <cuda_fp16.h>
#include <cstdint>

// Spatial RNN, 4 dirs, R=8 steps, C=64. f16 mma.sync (f16 accum) + LDSM/STSM.
// x:(8,192,192,64) fp32; W_*:(64,64); out:(8,192,192,256)
//
// R13: 4-warp CTAs (128 thr), warp tile m48 x n64 -> zero A duplication.
// State buffers: 128B row stride with SW128 XOR swizzle (conflict-free
// LDSM/STSM), 3 buffers x 24832B = 74.5KB -> 3 CTAs/SM (12 warps, 3
// independent barrier streams, 128-thread barriers). Packed f16x2
// accumulators; B (both dirs) in registers; 2 dirs sequential per CTA.

#define BUFB (194 * 128)            // 24832 bytes per buffer
#define SMEM_DYN (3 * BUFB + 64)    // 74560

static __device__ __forceinline__ uint32_t smem_u32(const void* p) {
    uint32_t a;
    asm("{ .reg .u64 t; cvta.to.shared.u64 t, %1; cvt.u32.u64 %0, t; }" : "=r"(a) : "l"(p));
    return a;
}
static __device__ __forceinline__ uint32_t pkh2(float lo, float hi) {
    uint32_t r;
    asm("cvt.rn.f16x2.f32 %0, %1, %2;" : "=r"(r) : "f"(hi), "f"(lo));
    return r;
}
static __device__ __forceinline__ uint32_t hmax2z(uint32_t v) {
    uint32_t r;
    asm("max.f16x2 %0, %1, %2;" : "=r"(r) : "r"(v), "r"(0u));
    return r;
}
static __device__ __forceinline__ uint32_t hadd2(uint32_t a, uint32_t b) {
    uint32_t r;
    asm("add.f16x2 %0, %1, %2;" : "=r"(r) : "r"(a), "r"(b));
    return r;
}
static __device__ __forceinline__ void unpkh2(uint32_t v, float& lo, float& hi) {
    asm("{ .reg .f16 l, h; mov.b32 {l, h}, %2; cvt.f32.f16 %0, l; cvt.f32.f16 %1, h; }"
        : "=f"(lo), "=f"(hi) : "r"(v));
}
static __device__ __forceinline__ void ldsm4(uint32_t a[4], uint32_t addr) {
    asm volatile("ldmatrix.sync.aligned.m8n8.x4.shared.b16 {%0,%1,%2,%3}, [%4];"
                 : "=r"(a[0]), "=r"(a[1]), "=r"(a[2]), "=r"(a[3]) : "r"(addr));
}
static __device__ __forceinline__ void stsm4(uint32_t addr, uint32_t r0, uint32_t r1,
                                             uint32_t r2, uint32_t r3) {
    asm volatile("stmatrix.sync.aligned.m8n8.x4.shared.b16 [%0], {%1,%2,%3,%4};"
                 :: "r"(addr), "r"(r0), "r"(r1), "r"(r2), "r"(r3) : "memory");
}
static __device__ __forceinline__ void mma16816h(uint32_t c[2], const uint32_t a[4],
                                                 const uint32_t b[2]) {
    asm volatile(
        "mma.sync.aligned.m16n8k16.row.col.f16.f16.f16.f16 "
        "{%0,%1}, {%2,%3,%4,%5}, {%6,%7}, {%0,%1};"
        : "+r"(c[0]), "+r"(c[1])
        : "r"(a[0]), "r"(a[1]), "r"(a[2]), "r"(a[3]), "r"(b[0]), "r"(b[1]));
}
static __device__ __forceinline__ void sts128(uint32_t addr, uint32_t a, uint32_t b,
                                              uint32_t c, uint32_t d) {
    asm volatile("st.shared.v4.b32 [%0], {%1,%2,%3,%4};"
                 :: "r"(addr), "r"(a), "r"(b), "r"(c), "r"(d) : "memory");
}
static __device__ __forceinline__ void sts32(uint32_t addr, uint32_t v) {
    asm volatile("st.shared.b32 [%0], %1;" :: "r"(addr), "r"(v) : "memory");
}

extern "C" __global__ void __launch_bounds__(128, 3)
rnn_kernel(const float* __restrict__ x,
           const float* __restrict__ W_left, const float* __restrict__ W_right,
           const float* __restrict__ W_up,   const float* __restrict__ W_down,
           float* __restrict__ out)
{
    extern __shared__ char dsm[];
    const uint32_t base = (smem_u32(dsm) + 15u) & ~15u;
    const uint32_t Xb = base;              // persistent f16 x (swizzled)
    const uint32_t P0 = base + BUFB;       // ping-pong state (swizzled)
    const uint32_t P1 = base + 2 * BUFB;

    const int tid  = threadIdx.x;
    const int lane = tid & 31;
    const int warp = tid >> 5;             // 0..3, m0 = 48*warp
    const int gID  = lane >> 2;
    const int tg   = lane & 3;
    const int m0   = warp * 48;

    // --- geometry ---
    long inBase, outBase;
    int pixIn, pixOut, chBase;
    const float *Wfp, *Wbp;
    {
        int l = blockIdx.x;
        if (l < 1536) {                            // horizontal row
            inBase  = (long)l * (192 * 64);
            outBase = (long)l * (192 * 256);
            pixIn = 64;  pixOut = 256;  chBase = 0;
            Wfp = W_left;  Wbp = W_right;
        } else {                                    // vertical column
            int l2 = l - 1536;
            int b = l2 / 192, w = l2 % 192;
            inBase  = (long)b * (192 * 192 * 64)  + (long)w * 64;
            outBase = (long)b * (192 * 192 * 256) + (long)w * 256;
            pixIn = 192 * 64;  pixOut = 192 * 256;  chBase = 128;
            Wfp = W_up;  Wbp = W_down;
        }
    }
    const float* xl = x + inBase;
    float* ol = out + outBase;

    // --- zero guard rows (rows 0 and 193 of all three buffers) ---
    if (tid < 32) {
        sts32(Xb + tid * 4, 0);  sts32(Xb + 193 * 128 + tid * 4, 0);
        sts32(P0 + tid * 4, 0);  sts32(P0 + 193 * 128 + tid * 4, 0);
        sts32(P1 + tid * 4, 0);  sts32(P1 + 193 * 128 + tid * 4, 0);
    }

    // --- load x (f16) into Xb rows 1..192, SW128-swizzled ---
    #pragma unroll
    for (int p = 0; p < 6; p++) {
        int i = tid + p * 128;                  // 0..767
        int r = i >> 2;
        int c0 = (i & 3) * 16;                  // float col base
        const float* xp = xl + (long)r * pixIn + c0;
        uint32_t h[8];
        #pragma unroll
        for (int j = 0; j < 4; j++) {
            float4 v = *reinterpret_cast<const float4*>(xp + j * 4);
            h[2 * j]     = pkh2(v.x, v.y);
            h[2 * j + 1] = pkh2(v.z, v.w);
        }
        uint32_t rx = (uint32_t)(((r + 1) & 7) << 4);
        uint32_t rowb = Xb + (uint32_t)(r + 1) * 128;
        sts128(rowb + ((uint32_t)(c0 * 2) ^ rx),      h[0], h[1], h[2], h[3]);
        sts128(rowb + ((uint32_t)(c0 * 2 + 16) ^ rx), h[4], h[5], h[6], h[7]);
    }

    // LDSM/STSM per-thread row/col decomposition
    const int lrow = (lane & 7) + ((lane >> 3) & 1) * 8;
    const int lcol = (lane >> 4) * 16;
    const int stRow = m0 + lrow + 1;
    const uint32_t rxS = (uint32_t)((stRow & 7) << 4);
    const uint32_t stBase = (uint32_t)(stRow * 128);

    __syncthreads();

    #pragma unroll 1
    for (int dir = 0; dir < 2; dir++) {
        const float* Wg = dir ? Wbp : Wfp;
        const int shift = dir ? 1 : -1;            // fwd reads r-1, bwd reads r+1

        // --- B fragments (full n64) in registers, from gmem (L2-hot) ---
        uint32_t b[4][8][2];
        #pragma unroll
        for (int kc = 0; kc < 4; kc++)
            #pragma unroll
            for (int nt = 0; nt < 8; nt++) {
                int k0 = kc * 16 + 2 * tg;
                int n  = nt * 8 + gID;
                b[kc][nt][0] = pkh2(__ldg(&Wg[(k0)     * 64 + n]), __ldg(&Wg[(k0 + 1) * 64 + n]));
                b[kc][nt][1] = pkh2(__ldg(&Wg[(k0 + 8) * 64 + n]), __ldg(&Wg[(k0 + 9) * 64 + n]));
            }

        uint32_t acc[3][8][2];                     // packed f16x2 accumulators
        #pragma unroll
        for (int mt = 0; mt < 3; mt++)
            #pragma unroll
            for (int nt = 0; nt < 8; nt++) {
                acc[mt][nt][0] = 0u;  acc[mt][nt][1] = 0u;
            }

        const int ldRow = m0 + lrow + shift + 1;
        const uint32_t rxL = (uint32_t)((ldRow & 7) << 4);
        const uint32_t ldBase = (uint32_t)(ldRow * 128);

        uint32_t src = Xb, dst = P0;

        #pragma unroll 1
        for (int s = 0; s < 8; s++) {
            const bool last = (s == 7);

            #pragma unroll
            for (int mt = 0; mt < 3; mt++) {
                uint32_t a[4][4];
                #pragma unroll
                for (int kc = 0; kc < 4; kc++)
                    ldsm4(a[kc], src + ldBase + mt * 2048 +
                                 ((uint32_t)(lcol + kc * 32) ^ rxL));

                uint32_t Cf[8][2];
                #pragma unroll
                for (int nt = 0; nt < 8; nt++) { Cf[nt][0] = 0u; Cf[nt][1] = 0u; }

                #pragma unroll
                for (int kc = 0; kc < 4; kc++)
                    #pragma unroll
                    for (int nt = 0; nt < 8; nt++)
                        mma16816h(Cf[nt], a[kc], b[kc][nt]);

                // relu in place
                #pragma unroll
                for (int nt = 0; nt < 8; nt++) {
                    Cf[nt][0] = hmax2z(Cf[nt][0]);
                    Cf[nt][1] = hmax2z(Cf[nt][1]);
                }
                // state store first (shortens path to the barrier) ...
                if (!last) {
                    uint32_t sa = dst + stBase + mt * 2048;
                    #pragma unroll
                    for (int g = 0; g < 4; g++)
                        stsm4(sa + ((uint32_t)(lcol + g * 32) ^ rxS),
                              Cf[2 * g][0], Cf[2 * g][1],
                              Cf[2 * g + 1][0], Cf[2 * g + 1][1]);
                }
                // ... then accumulate
                #pragma unroll
                for (int nt = 0; nt < 8; nt++) {
                    acc[mt][nt][0] = hadd2(acc[mt][nt][0], Cf[nt][0]);
                    acc[mt][nt][1] = hadd2(acc[mt][nt][1], Cf[nt][1]);
                }
            }

            if (!last) __syncthreads();
            src = dst;
            dst = (dst == P0) ? P1 : P0;
        }

        // --- epilogue: out = x + acc ---
        const int cb = chBase + dir * 64;
        #pragma unroll
        for (int mt = 0; mt < 3; mt++) {
            #pragma unroll
            for (int hh = 0; hh < 2; hh++) {
                int gr = m0 + mt * 16 + gID + hh * 8;
                const float* xp = xl + (long)gr * pixIn;
                float* op = ol + (long)gr * pixOut + cb;
                #pragma unroll
                for (int nt = 0; nt < 8; nt++) {
                    int col = nt * 8 + 2 * tg;
                    float a0, a1;
                    unpkh2(acc[mt][nt][hh], a0, a1);
                    float2 xv = *reinterpret_cast<const float2*>(xp + col);
                    *reinterpret_cast<float2*>(op + col) =
                        make_float2(xv.x + a0, xv.y + a1);
                }
            }
        }
        __syncthreads();   // all P0/P1 reads done before next dir reuses them
    }
}

extern "C" void kernel_launch(void* const* d_in, const int* in_sizes, int n_in,
                              void* d_out, int out_size)
{
    const float* x  = (const float*)d_in[0];
    const float* wl = (const float*)d_in[1];
    const float* wr = (const float*)d_in[2];
    const float* wu = (const float*)d_in[3];
    const float* wd = (const float*)d_in[4];
    float* out = (float*)d_out;

    cudaFuncSetAttribute(rnn_kernel, cudaFuncAttributeMaxDynamicSharedMemorySize, SMEM_DYN);
    rnn_kernel<<<3072, 128, SMEM_DYN>>>(x, wl, wr, wu, wd, out);
}